// round 10
// baseline (speedup 1.0000x reference)
#include <cuda_runtime.h>
#include <cuda_bf16.h>
#include <cstdint>
#include <math.h>

#define FIELD 39
#define EMBD 8
#define MAXB 16384
#define D0 312
#define D0P 320
#define D1 512
#define D2 256
#define D3 128

#define KW0 (D0P / 2)    // 160 words per h0 row
#define KW1 (D1 / 2)     // 256
#define KW2 (D2 / 2)     // 128

// Scratch (allocation-free rule). Activations packed bf16x2, k-contiguous.
__device__ float    g_li[MAXB];
__device__ unsigned g_h0[MAXB * KW0];
__device__ unsigned g_h1[MAXB * KW1];
__device__ unsigned g_h2[MAXB * KW2];
// packed weights, layout [N][KW] (k-contiguous per output column)
__device__ unsigned g_w0p[D1 * KW0];
__device__ unsigned g_w1p[D2 * KW1];
__device__ unsigned g_w2p[D3 * KW2];

#define PACK_TOTAL (D1 * KW0 + D2 * KW1 + D3 * KW2)   // 163840

__device__ __forceinline__ unsigned pack_bf2(float a, float b) {
    __nv_bfloat162 p = __floats2bfloat162_rn(a, b);
    return *(unsigned*)&p;
}

// ---------------------------------------------------------------------------
// 1. fused prep kernel: block-range roles (gather | linear+inter | weight pack)
// ---------------------------------------------------------------------------
__global__ __launch_bounds__(256) void prep_kernel(
    const int* __restrict__ ids, const float* __restrict__ vals,
    const float* __restrict__ FM_W, const float* __restrict__ FM_V,
    const float* __restrict__ FM_B, const float* __restrict__ emb,
    const float* __restrict__ W0, const float* __restrict__ W1,
    const float* __restrict__ W2, int B, int gB, int lB)
{
    const int bid = blockIdx.x;
    const int tid = threadIdx.x;

    if (bid < gB) {
        int idx = bid * 256 + tid;
        if (idx >= B * 40) return;
        int b = idx / 40, f = idx % 40;
        uint4 o;
        if (f < FIELD) {
            int id = ids[b * FIELD + f];
            const float4* e = (const float4*)(emb + (size_t)id * EMBD);
            float4 e0 = e[0];
            float4 e1 = e[1];
            o.x = pack_bf2(e0.x, e0.y);
            o.y = pack_bf2(e0.z, e0.w);
            o.z = pack_bf2(e1.x, e1.y);
            o.w = pack_bf2(e1.z, e1.w);
        } else {
            o = make_uint4(0u, 0u, 0u, 0u);
        }
        *(uint4*)(g_h0 + (size_t)b * KW0 + f * 4) = o;
    } else if (bid < gB + lB) {
        __shared__ float Vi[FIELD][8][EMBD];
        __shared__ float Ss[FIELD * FIELD];
        for (int idx = tid; idx < FIELD * 64; idx += 256) {
            int i = idx / 64, r = idx % 64;
            long long off = (long long)i * (51000LL * 64LL) + r;
            Vi[i][r >> 3][r & 7] = FM_V[off];
        }
        __syncthreads();
        for (int idx = tid; idx < FIELD * FIELD; idx += 256) {
            int i = idx / FIELD, j = idx % FIELD;
            float s = 0.f;
            if (j > i) {
#pragma unroll
                for (int e = 0; e < EMBD; e++)
                    s += Vi[i][j & 7][e] * Vi[j][i & 7][e];
            }
            Ss[idx] = s;
        }
        __syncthreads();

        int b = (bid - gB) * 256 + tid;
        if (b >= B) return;
        float v[FIELD];
        float lin = 0.f;
#pragma unroll
        for (int f = 0; f < FIELD; f++) {
            v[f] = vals[b * FIELD + f];
            lin += FM_W[ids[b * FIELD + f]] * v[f];
        }
        float inter = 0.f;
#pragma unroll
        for (int i = 0; i < FIELD; i++) {
            float ti = 0.f;
#pragma unroll
            for (int j = i + 1; j < FIELD; j++)
                ti += Ss[i * FIELD + j] * v[j];
            inter += v[i] * ti;
        }
        g_li[b] = lin + inter + FM_B[0];
    } else {
        int p = (bid - gB - lB) * 256 + tid;
        if (p >= PACK_TOTAL) return;
        if (p < D1 * KW0) {
            int n = p / KW0, kp = p % KW0;
            int k = 2 * kp;
            float a = (k     < D0) ? W0[(size_t)k * D1 + n]       : 0.f;
            float c = (k + 1 < D0) ? W0[(size_t)(k + 1) * D1 + n] : 0.f;
            g_w0p[p] = pack_bf2(a, c);
        } else if (p < D1 * KW0 + D2 * KW1) {
            int q = p - D1 * KW0;
            int n = q / KW1, kp = q % KW1;
            int k = 2 * kp;
            g_w1p[q] = pack_bf2(W1[(size_t)k * D2 + n], W1[(size_t)(k + 1) * D2 + n]);
        } else {
            int q = p - D1 * KW0 - D2 * KW1;
            int n = q / KW2, kp = q % KW2;
            int k = 2 * kp;
            g_w2p[q] = pack_bf2(W2[(size_t)k * D3 + n], W2[(size_t)(k + 1) * D3 + n]);
        }
    }
}

// ---------------------------------------------------------------------------
// common HMMA helpers
// ---------------------------------------------------------------------------
__device__ __forceinline__ void ldmx4(unsigned &r0, unsigned &r1, unsigned &r2,
                                      unsigned &r3, unsigned addr) {
    asm volatile("ldmatrix.sync.aligned.m8n8.x4.shared.b16 {%0,%1,%2,%3}, [%4];"
                 : "=r"(r0), "=r"(r1), "=r"(r2), "=r"(r3) : "r"(addr));
}

__device__ __forceinline__ void mma_bf16(float* c, const unsigned* a, const unsigned* b) {
    asm volatile(
        "mma.sync.aligned.m16n8k16.row.col.f32.bf16.bf16.f32 "
        "{%0,%1,%2,%3}, {%4,%5,%6,%7}, {%8,%9}, {%0,%1,%2,%3};"
        : "+f"(c[0]), "+f"(c[1]), "+f"(c[2]), "+f"(c[3])
        : "r"(a[0]), "r"(a[1]), "r"(a[2]), "r"(a[3]), "r"(b[0]), "r"(b[1]));
}

// ---------------------------------------------------------------------------
// 2. BIG GEMM for layers 0 & 1: BM=256, BN=128, BK=32 elems (16 words),
//    8 warps in 4x2, warp tile 64x64. 3-stage cp.async, swizzled, ldmatrix.
//    A packed [M][KW], Wp packed [N][KW], C packed [M][N/2]. Dynamic smem.
// ---------------------------------------------------------------------------
#define BIG_ASZ (256 * 16)   // words per A stage
#define BIG_BSZ (128 * 16)   // words per B stage
#define BIG_SMEM (3 * (BIG_ASZ + BIG_BSZ) * 4)   // 73728 bytes

__global__ __launch_bounds__(256, 1) void gemm_big(
    const unsigned* __restrict__ A, const unsigned* __restrict__ Wp,
    const float* __restrict__ bias, unsigned* __restrict__ C,
    int N, int KW)
{
    extern __shared__ unsigned sm[];

    const int t = threadIdx.x;
    const int lane = t & 31;
    const int warp = t >> 5;
    const int wm = (warp >> 1) * 64;   // 4 warp rows
    const int wn = (warp & 1) * 64;    // 2 warp cols
    const int bm = blockIdx.y * 256;
    const int bn = blockIdx.x * 128;

    const unsigned aBase = (unsigned)__cvta_generic_to_shared(sm);
    const unsigned bBase = aBase + 3 * BIG_ASZ * 4;
    const int nk = KW >> 4;            // 16 words = 32 elems per tile

    auto load_stage = [&](int st, int kt) {
        int kw0 = kt * 16;
#pragma unroll
        for (int i = 0; i < 4; i++) {           // A: 256 rows x 4 chunks
            int id = t + 256 * i;
            int row = id >> 2, c = id & 3;
            int pc = c ^ ((row >> 1) & 3);
            const unsigned* g = A + (size_t)(bm + row) * KW + kw0 + c * 4;
            unsigned s = aBase + (st * BIG_ASZ + row * 16 + pc * 4) * 4;
            asm volatile("cp.async.cg.shared.global [%0], [%1], 16;" :: "r"(s), "l"(g));
        }
#pragma unroll
        for (int i = 0; i < 2; i++) {           // B: 128 rows x 4 chunks
            int id = t + 256 * i;
            int row = id >> 2, c = id & 3;
            int pc = c ^ ((row >> 1) & 3);
            const unsigned* g = Wp + (size_t)(bn + row) * KW + kw0 + c * 4;
            unsigned s = bBase + (st * BIG_BSZ + row * 16 + pc * 4) * 4;
            asm volatile("cp.async.cg.shared.global [%0], [%1], 16;" :: "r"(s), "l"(g));
        }
    };

    float acc[4][8][4] = {};

    load_stage(0, 0);
    asm volatile("cp.async.commit_group;" ::: "memory");
    load_stage(1, 1);
    asm volatile("cp.async.commit_group;" ::: "memory");
    load_stage(2, 2);
    asm volatile("cp.async.commit_group;" ::: "memory");

    const int lrow = lane & 15;
    const int lsel = lane >> 4;

    for (int kt = 0; kt < nk; kt++) {
        asm volatile("cp.async.wait_group 2;" ::: "memory");
        __syncthreads();

        int pf = kt + 3;
        if (pf < nk) load_stage(pf % 3, pf);
        asm volatile("cp.async.commit_group;" ::: "memory");

        unsigned aOff = aBase + (kt % 3) * BIG_ASZ * 4;
        unsigned bOff = bBase + (kt % 3) * BIG_BSZ * 4;

#pragma unroll
        for (int s = 0; s < 2; s++) {           // two k16 steps per BK=32
            int lc = 2 * s + lsel;
            unsigned a[4][4], b[8][2];
#pragma unroll
            for (int p = 0; p < 4; p++) {       // 64 n-cols = 4 ldmx4
                int n = wn + p * 16 + lrow;
                int pc = lc ^ ((n >> 1) & 3);
                unsigned r0, r1, r2, r3;
                ldmx4(r0, r1, r2, r3, bOff + (n * 16 + pc * 4) * 4);
                b[2 * p][0] = r0;  b[2 * p + 1][0] = r1;
                b[2 * p][1] = r2;  b[2 * p + 1][1] = r3;
            }
#pragma unroll
            for (int mt = 0; mt < 4; mt++) {    // 64 m-rows = 4 ldmx4
                int m = wm + mt * 16 + lrow;
                int pc = lc ^ ((m >> 1) & 3);
                ldmx4(a[mt][0], a[mt][1], a[mt][2], a[mt][3],
                      aOff + (m * 16 + pc * 4) * 4);
            }
#pragma unroll
            for (int mt = 0; mt < 4; mt++)
#pragma unroll
                for (int nt = 0; nt < 8; nt++)
                    mma_bf16(acc[mt][nt], a[mt], b[nt]);
        }
        __syncthreads();
    }

    // epilogue: bias + relu, pack bf16x2
    const int r = lane >> 2, cc = lane & 3;
    const int NW = N >> 1;
#pragma unroll
    for (int nt = 0; nt < 8; nt++) {
        int col = bn + wn + nt * 8 + 2 * cc;
        float b0 = bias[col], b1 = bias[col + 1];
        int cw = col >> 1;
#pragma unroll
        for (int mt = 0; mt < 4; mt++) {
            int row0 = bm + wm + mt * 16 + r;
            unsigned o0 = pack_bf2(fmaxf(acc[mt][nt][0] + b0, 0.f),
                                   fmaxf(acc[mt][nt][1] + b1, 0.f));
            unsigned o1 = pack_bf2(fmaxf(acc[mt][nt][2] + b0, 0.f),
                                   fmaxf(acc[mt][nt][3] + b1, 0.f));
            C[(size_t)row0 * NW + cw] = o0;
            C[(size_t)(row0 + 8) * NW + cw] = o1;
        }
    }
}

// ---------------------------------------------------------------------------
// 3. last GEMM + head (verbatim R7 machinery): BM=64, BN=128, warp 32x32.
// ---------------------------------------------------------------------------
#define SSTG 3
#define ASTG (64 * 16)
#define BSTG (128 * 16)

struct Frag { float acc[2][4][4]; };

__device__ __forceinline__ void gemm_mainloop(
    const unsigned* __restrict__ A, const unsigned* __restrict__ Wp,
    int KW, int bm, int bn, unsigned* AsBase, unsigned* BsBase,
    int t, int lane, int wm, int wn, Frag &F)
{
    const unsigned aBase = (unsigned)__cvta_generic_to_shared(AsBase);
    const unsigned bBase = (unsigned)__cvta_generic_to_shared(BsBase);
    const int nk = KW >> 4;

    auto load_stage = [&](int st, int kt) {
        int kw0 = kt * 16;
        {
            int m = t >> 2, c = t & 3;
            int pc = c ^ ((m >> 1) & 3);
            const unsigned* g = A + (size_t)(bm + m) * KW + kw0 + c * 4;
            unsigned s = aBase + (st * ASTG + m * 16 + pc * 4) * 4;
            asm volatile("cp.async.cg.shared.global [%0], [%1], 16;" :: "r"(s), "l"(g));
        }
#pragma unroll
        for (int i = 0; i < 2; i++) {
            int idx = t + 256 * i;
            int n = idx >> 2, c = idx & 3;
            int pc = c ^ ((n >> 1) & 3);
            const unsigned* g = Wp + (size_t)(bn + n) * KW + kw0 + c * 4;
            unsigned s = bBase + (st * BSTG + n * 16 + pc * 4) * 4;
            asm volatile("cp.async.cg.shared.global [%0], [%1], 16;" :: "r"(s), "l"(g));
        }
    };

    load_stage(0, 0);
    asm volatile("cp.async.commit_group;" ::: "memory");
    if (nk > 1) load_stage(1, 1);
    asm volatile("cp.async.commit_group;" ::: "memory");

    const int lrow = lane & 15;
    const int lsel = lane >> 4;

    for (int kt = 0; kt < nk; kt++) {
        asm volatile("cp.async.wait_group 1;" ::: "memory");
        __syncthreads();

        int pf = kt + SSTG - 1;
        if (pf < nk) load_stage(pf % SSTG, pf);
        asm volatile("cp.async.commit_group;" ::: "memory");

        unsigned aOff = aBase + (kt % SSTG) * ASTG * 4;
        unsigned bOff = bBase + (kt % SSTG) * BSTG * 4;

#pragma unroll
        for (int s = 0; s < 2; s++) {
            unsigned a[2][4], b[4][2];
            int lc = 2 * s + lsel;
#pragma unroll
            for (int p = 0; p < 2; p++) {
                int n = wn + p * 16 + lrow;
                int pc = lc ^ ((n >> 1) & 3);
                unsigned r0, r1, r2, r3;
                ldmx4(r0, r1, r2, r3, bOff + (n * 16 + pc * 4) * 4);
                b[2 * p][0] = r0;  b[2 * p + 1][0] = r1;
                b[2 * p][1] = r2;  b[2 * p + 1][1] = r3;
            }
#pragma unroll
            for (int mt = 0; mt < 2; mt++) {
                int m = wm + mt * 16 + lrow;
                int pc = lc ^ ((m >> 1) & 3);
                ldmx4(a[mt][0], a[mt][1], a[mt][2], a[mt][3],
                      aOff + (m * 16 + pc * 4) * 4);
            }
#pragma unroll
            for (int mt = 0; mt < 2; mt++)
#pragma unroll
                for (int nt = 0; nt < 4; nt++)
                    mma_bf16(F.acc[mt][nt], a[mt], b[nt]);
        }
    }
}

__global__ __launch_bounds__(256, 3) void gemm_last_head(
    const unsigned* __restrict__ A, const unsigned* __restrict__ Wp,
    const float* __restrict__ bias, const float* __restrict__ outW,
    const float* __restrict__ outB, float* __restrict__ out, int KW)
{
    __shared__ unsigned As[SSTG * ASTG];
    __shared__ unsigned Bs[SSTG * BSTG];
    __shared__ float red[64][4];

    const int t = threadIdx.x;
    const int lane = t & 31;
    const int warp = t >> 5;
    const int wm = (warp >> 2) * 32;
    const int wn = (warp & 3) * 32;
    const int bm = blockIdx.x * 64;

    Frag F = {};
    gemm_mainloop(A, Wp, KW, bm, 0, As, Bs, t, lane, wm, wn, F);

    const int r = lane >> 2, cc = lane & 3;
#pragma unroll
    for (int mt = 0; mt < 2; mt++) {
        float p0 = 0.f, p1 = 0.f;
#pragma unroll
        for (int nt = 0; nt < 4; nt++) {
            int col = wn + nt * 8 + 2 * cc;
            float b0 = bias[col], b1 = bias[col + 1];
            float w0 = outW[col], w1 = outW[col + 1];
            p0 += fmaxf(F.acc[mt][nt][0] + b0, 0.f) * w0
                + fmaxf(F.acc[mt][nt][1] + b1, 0.f) * w1;
            p1 += fmaxf(F.acc[mt][nt][2] + b0, 0.f) * w0
                + fmaxf(F.acc[mt][nt][3] + b1, 0.f) * w1;
        }
        p0 += __shfl_xor_sync(0xffffffffu, p0, 1);
        p0 += __shfl_xor_sync(0xffffffffu, p0, 2);
        p1 += __shfl_xor_sync(0xffffffffu, p1, 1);
        p1 += __shfl_xor_sync(0xffffffffu, p1, 2);
        if (cc == 0) {
            red[wm + mt * 16 + r][warp & 3] = p0;
            red[wm + mt * 16 + r + 8][warp & 3] = p1;
        }
    }
    __syncthreads();
    if (t < 64) {
        float s = red[t][0] + red[t][1] + red[t][2] + red[t][3];
        float x = s + outB[0] + g_li[bm + t];
        out[bm + t] = 1.f / (1.f + expf(-x));
    }
}

// ---------------------------------------------------------------------------
extern "C" void kernel_launch(void* const* d_in, const int* in_sizes, int n_in,
                              void* d_out, int out_size)
{
    const int*   feat_ids  = (const int*)  d_in[0];
    const float* feat_vals = (const float*)d_in[1];
    const float* FM_W      = (const float*)d_in[2];
    const float* FM_V      = (const float*)d_in[3];
    const float* FM_B      = (const float*)d_in[4];
    const float* emb       = (const float*)d_in[5];
    const float* W0        = (const float*)d_in[6];
    const float* B0        = (const float*)d_in[7];
    const float* W1        = (const float*)d_in[8];
    const float* B1        = (const float*)d_in[9];
    const float* W2        = (const float*)d_in[10];
    const float* B2        = (const float*)d_in[11];
    const float* outW      = (const float*)d_in[12];
    const float* outB      = (const float*)d_in[13];
    float* out = (float*)d_out;

    int B = in_sizes[0] / FIELD;
    if (B > MAXB) B = MAXB;

    unsigned *h0, *h1, *h2, *w0p, *w1p, *w2p;
    cudaGetSymbolAddress((void**)&h0, g_h0);
    cudaGetSymbolAddress((void**)&h1, g_h1);
    cudaGetSymbolAddress((void**)&h2, g_h2);
    cudaGetSymbolAddress((void**)&w0p, g_w0p);
    cudaGetSymbolAddress((void**)&w1p, g_w1p);
    cudaGetSymbolAddress((void**)&w2p, g_w2p);

    cudaFuncSetAttribute(gemm_big,
                         cudaFuncAttributeMaxDynamicSharedMemorySize, BIG_SMEM);

    int gB = (B * 40 + 255) / 256;
    int lB = (B + 255) / 256;
    int pB = (PACK_TOTAL + 255) / 256;

    prep_kernel<<<gB + lB + pB, 256>>>(feat_ids, feat_vals, FM_W, FM_V, FM_B, emb,
                                       W0, W1, W2, B, gB, lB);

    gemm_big<<<dim3(D1 / 128, B / 256), 256, BIG_SMEM>>>(h0, w0p, B0, h1, D1, KW0);
    gemm_big<<<dim3(D2 / 128, B / 256), 256, BIG_SMEM>>>(h1, w1p, B1, h2, D2, KW1);
    gemm_last_head<<<B / 64, 256>>>(h2, w2p, B2, outW, outB, out, KW2);
}